// round 15
// baseline (speedup 1.0000x reference)
#include <cuda_runtime.h>
#include <cuda_fp16.h>
#include <cstdint>

#define N_  2048
#define E_  8192
#define ND_ 32
#define ED_ 16
#define H_  128
#define G_  128
#define L_  3
#define KD_ 18          // 16 edge dims + edge bias + root_W
#define ZHW_ (17 * H_)  // 2176 halves per node (conv chunks)
#define BN_EPS 1e-5f

#define TTILES_ (L_ * KD_ * 16)   // 864 transpose tiles (32x32), 16 per chunk

// ---------------- device scratch ----------------
__device__ float  g_h[N_ * H_];
__device__ __half g_hh[N_ * H_];                // fp16 copy of h (GEMM A input)
__device__ float  g_xnew[N_ * H_];
__device__ float  g_agg3[L_ * N_ * H_];
__device__ float  g_deg[N_];
__device__ float  g_stats[L_ * 2 * H_];
__device__ float  g_pool[G_ * H_];
__device__ float  g_gcnt[G_];
__device__ __half g_zh[N_ * ZHW_];              // fp16 conv-chunk z, 8.9MB
__device__ float  g_zroot[N_ * H_];             // fp32 root chunk
__device__ __half g_eWt[L_ * KD_ * H_ * H_];    // fp16, [l][d][n=o][k=i]
__device__ int    g_soff[N_];
__device__ int4   g_einfo[E_];                  // (src, dst, e, pad) per sorted pos

// ---------------- helpers ----------------
#define LDSM4(r0, r1, r2, r3, addr)                                          \
    asm volatile("ldmatrix.sync.aligned.m8n8.x4.shared.b16 {%0,%1,%2,%3}, [%4];" \
                 : "=r"(r0), "=r"(r1), "=r"(r2), "=r"(r3) : "r"(addr))

// fp16 mma: D(f32) += A(f16 m16k16) * B(f16 k16n8)
#define MMA_F16(c, a, b0, b1)                                                \
    asm volatile("mma.sync.aligned.m16n8k16.row.col.f32.f16.f16.f32 "        \
                 "{%0,%1,%2,%3}, {%4,%5,%6,%7}, {%8,%9}, {%0,%1,%2,%3};"     \
                 : "+f"((c)[0]), "+f"((c)[1]), "+f"((c)[2]), "+f"((c)[3])    \
                 : "r"((a)[0]), "r"((a)[1]), "r"((a)[2]), "r"((a)[3]),       \
                   "r"(b0), "r"(b1))

#define CPA16(dst, src)                                                       \
    asm volatile("cp.async.cg.shared.global [%0], [%1], 16;"                  \
                 :: "r"(dst), "l"(src))

// ---------------- init: tiled eWt transpose(+fp16) + zeros + node encoder ----------------
__global__ void __launch_bounds__(256)
init_kernel(const float* __restrict__ edge_W,
            const float* __restrict__ edge_b,
            const float* __restrict__ root_W,
            const float* __restrict__ x,
            const float* __restrict__ nW,
            const float* __restrict__ nb) {
    int b = blockIdx.x;
    if (b < TTILES_) {
        __shared__ float tile[32][33];
        int c  = b >> 4;
        int t  = b & 15;
        int l  = c / KD_, d = c - l * KD_;
        int n0 = (t >> 2) * 32;
        int k0 = (t & 3) * 32;
        const float* srcp;
        if (d < 16)       srcp = edge_W + ((size_t)(l * 16 + d) << 14);
        else if (d == 16) srcp = edge_b + ((size_t)l << 14);
        else              srcp = root_W + ((size_t)l << 14);
        int tx = threadIdx.x & 31, ty = threadIdx.x >> 5;
#pragma unroll
        for (int q = 0; q < 4; ++q) {
            int kk = k0 + ty + q * 8;
            tile[ty + q * 8][tx] = srcp[kk * H_ + n0 + tx];
        }
        __syncthreads();
        __half* dstp = g_eWt + ((size_t)c << 14);
#pragma unroll
        for (int q = 0; q < 4; ++q) {
            int nn = n0 + ty + q * 8;
            dstp[nn * H_ + k0 + tx] = __float2half_rn(tile[tx][ty + q * 8]);
        }
        return;
    }
    int i = (b - TTILES_) * 256 + threadIdx.x;  // covers L*N*H
    if (i < L_ * N_ * H_)  g_agg3[i] = 0.f;
    if (i < G_ * H_)       g_pool[i] = 0.f;
    if (i < L_ * 2 * H_)   g_stats[i] = 0.f;
    if (i < N_ * H_) {
        int n = i >> 7, o = i & 127;
        const float* xr = x + n * ND_;
        float acc = nb[o];
#pragma unroll
        for (int k = 0; k < ND_; ++k) acc += xr[k] * nW[k * H_ + o];
        g_h[i]  = acc;
        g_hh[i] = __float2half_rn(acc);
    }
}

// ---------------- sort: src counting-sort + deg + gcnt, one block ----------------
__global__ void __launch_bounds__(1024)
sort_kernel(const int* __restrict__ edge_index, const int* __restrict__ batch) {
    __shared__ int sa[2048], sb[2048], sc_[2048], cur[2048];
    __shared__ float gcnt[G_];
    int t = threadIdx.x;
#pragma unroll
    for (int q = 0; q < 2; ++q) {
        int i = t + q * 1024;
        sa[i] = 0; sb[i] = 0; cur[i] = 0;
    }
    if (t < G_) gcnt[t] = 0.f;
    __syncthreads();
#pragma unroll
    for (int q = 0; q < 8; ++q) {
        int e = t + q * 1024;
        atomicAdd(&sa[edge_index[e]], 1);
        atomicAdd(&sb[edge_index[E_ + e]], 1);
    }
#pragma unroll
    for (int q = 0; q < 2; ++q) {
        int n = t + q * 1024;
        atomicAdd(&gcnt[batch[n]], 1.f);
    }
    __syncthreads();
    int *s1 = sa, *d1 = sc_;
#pragma unroll
    for (int off = 1; off < 2048; off <<= 1) {
#pragma unroll
        for (int q = 0; q < 2; ++q) {
            int i = t + q * 1024;
            d1[i] = s1[i] + (i >= off ? s1[i - off] : 0);
        }
        __syncthreads();
        int* tmp = s1; s1 = d1; d1 = tmp;
    }
#pragma unroll
    for (int q = 0; q < 2; ++q) {
        int i = t + q * 1024;
        g_soff[i] = i ? s1[i - 1] : 0;
        g_deg[i]  = (float)sb[i];
    }
    if (t < G_) g_gcnt[t] = gcnt[t];
    __syncthreads();
#pragma unroll
    for (int q = 0; q < 8; ++q) {
        int e = t + q * 1024;
        int src = edge_index[e];
        int dst = edge_index[E_ + e];
        int pos = (src ? s1[src - 1] : 0) + atomicAdd(&cur[src], 1);
        g_einfo[pos] = make_int4(src, dst, e, 0);
    }
}

// ---------------- zgemm: z = g_hh @ eWt, fp16 MMA, K-chunk pipelined ----------------
#define ZSA 136                         // halves per smem row (128 + 8 pad)
#define ZSMEM_B ((256 + 128) * ZSA * 2) // ~102 KB

__global__ void __launch_bounds__(256, 1)
zgemm_kernel(const __half* __restrict__ eWt) {
    extern __shared__ __half smh[];
    const int tid  = threadIdx.x;
    const int lane = tid & 31;
    const int wid  = tid >> 5;
    const int wm   = wid >> 1;
    const int wn   = wid & 1;
    const int m0   = blockIdx.x * 256;
    const int d    = blockIdx.y;

    const uint32_t smb = (uint32_t)__cvta_generic_to_shared(smh);
    const uint32_t boff = 256 * ZSA * 2;     // B base byte offset
    const __half* Bg = eWt + ((size_t)d << 14);

    // ---- stage A+B in 4 K-chunks of 32 halves (64B/row), one group each ----
#pragma unroll
    for (int c = 0; c < 4; ++c) {
        const int kc = c * 32;               // halves
        // A: 256 rows x 4 chunks of 8 halves (16B) -> 1024 cp / 4 per thread
#pragma unroll
        for (int jj = 0; jj < 4; ++jj) {
            int idx = tid + jj * 256;
            int r = idx >> 2, f8 = (idx & 3) << 3;
            uint32_t dst = smb + (r * ZSA + kc + f8) * 2;
            CPA16(dst, g_hh + (m0 + r) * H_ + kc + f8);
        }
        // B: 128 rows x 4 chunks -> 512 cp / 2 per thread
#pragma unroll
        for (int jj = 0; jj < 2; ++jj) {
            int idx = tid + jj * 256;
            int r = idx >> 2, f8 = (idx & 3) << 3;
            uint32_t dst = smb + boff + (r * ZSA + kc + f8) * 2;
            CPA16(dst, Bg + r * H_ + kc + f8);
        }
        asm volatile("cp.async.commit_group;");
    }

    // ldmatrix addresses: mrow covers 0-7/8-15 per lane octet; coff = 8-half col group
    const int mrow = (lane & 7) + ((lane >> 3) & 1) * 8;
    const int coff = (lane >> 4) * 8;        // halves
    uint32_t aad[4], bad[4];
#pragma unroll
    for (int mt = 0; mt < 4; ++mt)
        aad[mt] = smb + ((wm * 64 + mt * 16 + mrow) * ZSA + coff) * 2;
#pragma unroll
    for (int nt = 0; nt < 4; ++nt)
        bad[nt] = smb + boff + ((wn * 64 + nt * 16 + mrow) * ZSA + coff) * 2;

    float acc[4][8][4];
#pragma unroll
    for (int mt = 0; mt < 4; ++mt)
#pragma unroll
        for (int j = 0; j < 8; ++j)
#pragma unroll
            for (int p = 0; p < 4; ++p) acc[mt][j][p] = 0.f;

    uint32_t Af[2][4][4], Bf[2][4][4];

#define LOAD_STAGE(buf, ko)                                                   \
    do {                                                                      \
        _Pragma("unroll")                                                     \
        for (int mt = 0; mt < 4; ++mt)                                        \
            LDSM4(Af[buf][mt][0], Af[buf][mt][1], Af[buf][mt][2],             \
                  Af[buf][mt][3], aad[mt] + (ko));                            \
        _Pragma("unroll")                                                     \
        for (int nt = 0; nt < 4; ++nt)                                        \
            LDSM4(Bf[buf][nt][0], Bf[buf][nt][1], Bf[buf][nt][2],             \
                  Bf[buf][nt][3], bad[nt] + (ko));                            \
    } while (0)

    // ---- 4 chunks x 2 ksteps (k16 each), MMA overlaps in-flight staging ----
#pragma unroll
    for (int c = 0; c < 4; ++c) {
        if (c == 0) asm volatile("cp.async.wait_group 3;");
        else if (c == 1) asm volatile("cp.async.wait_group 2;");
        else if (c == 2) asm volatile("cp.async.wait_group 1;");
        else asm volatile("cp.async.wait_group 0;");
        __syncthreads();
        LOAD_STAGE(0, (uint32_t)(c * 2) * 32);       // 16 halves = 32B per kstep
#pragma unroll
        for (int ks = 0; ks < 2; ++ks) {
            const int cur = ks & 1;
            if (ks < 1) LOAD_STAGE(1, (uint32_t)(c * 2 + 1) * 32);
#pragma unroll
            for (int nt = 0; nt < 4; ++nt)
#pragma unroll
                for (int mt = 0; mt < 4; ++mt) {
                    MMA_F16(acc[mt][2 * nt],     Af[cur][mt], Bf[cur][nt][0], Bf[cur][nt][2]);
                    MMA_F16(acc[mt][2 * nt + 1], Af[cur][mt], Bf[cur][nt][1], Bf[cur][nt][3]);
                }
        }
    }
#undef LOAD_STAGE

    // ---- epilogue: conv chunks -> fp16 g_zh, root chunk -> fp32 g_zroot ----
    if (d < 17) {
#pragma unroll
        for (int mt = 0; mt < 4; ++mt) {
            int r = m0 + wm * 64 + mt * 16 + (lane >> 2);
            __half* zr0 = g_zh + (size_t)r * ZHW_ + d * H_;
            __half* zr1 = zr0 + 8 * ZHW_;
#pragma unroll
            for (int j = 0; j < 8; ++j) {
                int col = wn * 64 + (j >> 1) * 16 + (j & 1) * 8 + (lane & 3) * 2;
                *reinterpret_cast<__half2*>(zr0 + col) =
                    __floats2half2_rn(acc[mt][j][0], acc[mt][j][1]);
                *reinterpret_cast<__half2*>(zr1 + col) =
                    __floats2half2_rn(acc[mt][j][2], acc[mt][j][3]);
            }
        }
    } else {
#pragma unroll
        for (int mt = 0; mt < 4; ++mt) {
            int r = m0 + wm * 64 + mt * 16 + (lane >> 2);
            float* zr0 = g_zroot + (size_t)r * H_;
            float* zr1 = zr0 + 8 * H_;
#pragma unroll
            for (int j = 0; j < 8; ++j) {
                int col = wn * 64 + (j >> 1) * 16 + (j & 1) * 8 + (lane & 3) * 2;
                *reinterpret_cast<float2*>(zr0 + col) = make_float2(acc[mt][j][0], acc[mt][j][1]);
                *reinterpret_cast<float2*>(zr1 + col) = make_float2(acc[mt][j][2], acc[mt][j][3]);
            }
        }
    }
}

// ---------------- combine: warp per edge, fp16 gather, v4 reduction ----------------
__global__ void __launch_bounds__(256)
combine_kernel(const float* __restrict__ edge_attr,
               float* __restrict__ aggp) {
    int j    = blockIdx.x * 8 + (threadIdx.x >> 5);
    int lane = threadIdx.x & 31;
    int4 ei = g_einfo[j];                 // (src, dst, e)
    int src = ei.x, dst = ei.y, e = ei.z;

    float ea[16];
    {
        const float4* eap = reinterpret_cast<const float4*>(edge_attr + e * ED_);
#pragma unroll
        for (int q = 0; q < 4; ++q) {
            float4 v = eap[q];
            ea[4 * q] = v.x; ea[4 * q + 1] = v.y; ea[4 * q + 2] = v.z; ea[4 * q + 3] = v.w;
        }
    }

    const __half* zr = g_zh + (size_t)src * ZHW_ + lane * 4;
    float4 acc;
    {
        uint2 u = *reinterpret_cast<const uint2*>(zr + 16 * H_);   // bias chunk
        float2 f0 = __half22float2(*reinterpret_cast<__half2*>(&u.x));
        float2 f1 = __half22float2(*reinterpret_cast<__half2*>(&u.y));
        acc = make_float4(f0.x, f0.y, f1.x, f1.y);
    }
#pragma unroll
    for (int d = 0; d < 16; ++d) {
        uint2 u = *reinterpret_cast<const uint2*>(zr + d * H_);
        float2 f0 = __half22float2(*reinterpret_cast<__half2*>(&u.x));
        float2 f1 = __half22float2(*reinterpret_cast<__half2*>(&u.y));
        float a = ea[d];
        acc.x += a * f0.x; acc.y += a * f0.y;
        acc.z += a * f1.x; acc.w += a * f1.y;
    }
    float* ap = aggp + dst * H_ + lane * 4;
    asm volatile("red.global.add.v4.f32 [%0], {%1,%2,%3,%4};"
                 :: "l"(ap), "f"(acc.x), "f"(acc.y), "f"(acc.z), "f"(acc.w)
                 : "memory");
}

// ---------------- x_new = zroot + agg/deg + bias ; BN stats ----------------
__global__ void __launch_bounds__(256)
xnew_kernel(const float* __restrict__ cbias,
            const float* __restrict__ aggp, float* __restrict__ statp) {
    __shared__ float ps[128], pq[128];
    int o    = threadIdx.x & 127;
    int half = threadIdx.x >> 7;
    int r0   = blockIdx.x * 16 + half * 8;
    float cb = cbias[o];
    float s = 0.f, sq = 0.f;
#pragma unroll
    for (int r = 0; r < 8; ++r) {
        int n = r0 + r;
        float v = g_zroot[(size_t)n * H_ + o]
                + aggp[n * H_ + o] / fmaxf(g_deg[n], 1.f) + cb;
        g_xnew[n * H_ + o] = v;
        s += v;
        sq += v * v;
    }
    if (half) { ps[o] = s; pq[o] = sq; }
    __syncthreads();
    if (!half) {
        atomicAdd(&statp[o],      s  + ps[o]);
        atomicAdd(&statp[H_ + o], sq + pq[o]);
    }
}

// ---------------- BN + ReLU + residual (+ pool on last layer) ----------------
__global__ void bn_kernel(const float* __restrict__ gamma,
                          const float* __restrict__ beta,
                          const float* __restrict__ statp,
                          const int* __restrict__ batch, int last) {
    int idx = blockIdx.x * 256 + threadIdx.x;   // N*H threads
    int o = idx & (H_ - 1);
    float mu  = statp[o] * (1.f / N_);
    float var = statp[H_ + o] * (1.f / N_) - mu * mu;
    float v = (g_xnew[idx] - mu) * rsqrtf(var + BN_EPS) * gamma[o] + beta[o];
    float hv = g_h[idx] + fmaxf(v, 0.f);
    g_h[idx]  = hv;
    g_hh[idx] = __float2half_rn(hv);
    if (last) {
        int n = idx >> 7;
        atomicAdd(&g_pool[batch[n] * H_ + o], hv);
    }
}

// ---------------- classifier ----------------
__global__ void __launch_bounds__(64)
cls_kernel(const float* __restrict__ W1, const float* __restrict__ b1,
           const float* __restrict__ W2, const float* __restrict__ b2,
           float* __restrict__ out) {
    __shared__ float gv[H_];
    __shared__ float part[2];
    int g = blockIdx.x, j = threadIdx.x;
    float inv = 1.f / fmaxf(g_gcnt[g], 1.f);
    gv[j]      = g_pool[g * H_ + j] * inv;
    gv[j + 64] = g_pool[g * H_ + 64 + j] * inv;
    __syncthreads();
    float a = b1[j];
    for (int k = 0; k < H_; ++k) a += gv[k] * W1[k * 64 + j];
    float v = fmaxf(a, 0.f) * W2[j];
#pragma unroll
    for (int off = 16; off > 0; off >>= 1)
        v += __shfl_down_sync(0xffffffffu, v, off);
    if ((j & 31) == 0) part[j >> 5] = v;
    __syncthreads();
    if (j == 0) out[g] = part[0] + part[1] + b2[0];
}

// ---------------- launch ----------------
extern "C" void kernel_launch(void* const* d_in, const int* in_sizes, int n_in,
                              void* d_out, int out_size) {
    const float* x          = (const float*)d_in[0];
    const int*   edge_index = (const int*)  d_in[1];
    const float* edge_attr  = (const float*)d_in[2];
    const int*   batch      = (const int*)  d_in[3];
    const float* node_W     = (const float*)d_in[4];
    const float* node_b     = (const float*)d_in[5];
    const float* edge_W     = (const float*)d_in[6];
    const float* edge_b     = (const float*)d_in[7];
    const float* root_W     = (const float*)d_in[8];
    const float* conv_bias  = (const float*)d_in[9];
    const float* bn_gamma   = (const float*)d_in[10];
    const float* bn_beta    = (const float*)d_in[11];
    const float* cls_W1     = (const float*)d_in[12];
    const float* cls_b1     = (const float*)d_in[13];
    const float* cls_W2     = (const float*)d_in[14];
    const float* cls_b2     = (const float*)d_in[15];
    float* out = (float*)d_out;

    float*  d_agg3;  cudaGetSymbolAddress((void**)&d_agg3,  g_agg3);
    float*  d_stats; cudaGetSymbolAddress((void**)&d_stats, g_stats);
    __half* d_eWt;   cudaGetSymbolAddress((void**)&d_eWt,   g_eWt);

    cudaFuncSetAttribute((const void*)zgemm_kernel,
                         cudaFuncAttributeMaxDynamicSharedMemorySize, ZSMEM_B);

    init_kernel<<<TTILES_ + (L_ * N_ * H_) / 256, 256>>>(
        edge_W, edge_b, root_W, x, node_W, node_b);
    sort_kernel<<<1, 1024>>>(edge_index, batch);

    for (int l = 0; l < L_; ++l) {
        zgemm_kernel<<<dim3(N_ / 256, KD_), 256, ZSMEM_B>>>(
            d_eWt + (size_t)l * KD_ * H_ * H_);
        combine_kernel<<<E_ / 8, 256>>>(edge_attr,
                                        d_agg3 + (size_t)l * N_ * H_);
        xnew_kernel<<<N_ / 16, 256>>>(conv_bias + l * H_,
                                      d_agg3 + (size_t)l * N_ * H_,
                                      d_stats + l * 2 * H_);
        bn_kernel<<<(N_ * H_) / 256, 256>>>(bn_gamma + l * H_, bn_beta + l * H_,
                                            d_stats + l * 2 * H_, batch,
                                            l == L_ - 1);
    }

    cls_kernel<<<G_, 64>>>(cls_W1, cls_b1, cls_W2, cls_b2, out);
}

// round 16
// speedup vs baseline: 1.2652x; 1.2652x over previous
#include <cuda_runtime.h>
#include <cuda_fp16.h>
#include <cstdint>

#define N_  2048
#define E_  8192
#define ND_ 32
#define ED_ 16
#define H_  128
#define G_  128
#define L_  3
#define KD_ 18          // 16 edge dims + edge bias + root_W
#define ZHW_ (17 * H_)  // 2176 halves per node (conv chunks)
#define BN_EPS 1e-5f

#define TTILES_ (L_ * KD_ * 16)   // 864 transpose tiles (32x32), 16 per chunk

// ---------------- device scratch ----------------
__device__ float  g_h[N_ * H_];
__device__ float  g_ht[N_ * H_];                // tf32-rounded copy of h
__device__ float  g_xnew[N_ * H_];
__device__ float  g_agg3[L_ * N_ * H_];
__device__ float  g_deg[N_];
__device__ float  g_stats[L_ * 2 * H_];
__device__ float  g_pool[G_ * H_];
__device__ float  g_gcnt[G_];
__device__ __half g_zh[N_ * ZHW_];              // fp16 conv-chunk z, 8.9MB
__device__ float  g_zroot[N_ * H_];             // fp32 root chunk
__device__ float  g_eWt[L_ * KD_ * H_ * H_];    // tf32, [l][d][n=o][k=i]
__device__ int    g_soff[N_];
__device__ int4   g_einfo[E_];                  // (src, dst, e, pad) per sorted pos

// ---------------- helpers ----------------
__device__ __forceinline__ float tf32r(float x) {
    uint32_t u;
    asm("cvt.rna.tf32.f32 %0, %1;" : "=r"(u) : "f"(x));
    return __uint_as_float(u);
}

#define LDSM4(r0, r1, r2, r3, addr)                                          \
    asm volatile("ldmatrix.sync.aligned.m8n8.x4.shared.b16 {%0,%1,%2,%3}, [%4];" \
                 : "=r"(r0), "=r"(r1), "=r"(r2), "=r"(r3) : "r"(addr))

#define MMA_TF32(c, a, b0, b1)                                               \
    asm volatile("mma.sync.aligned.m16n8k8.row.col.f32.tf32.tf32.f32 "       \
                 "{%0,%1,%2,%3}, {%4,%5,%6,%7}, {%8,%9}, {%0,%1,%2,%3};"     \
                 : "+f"((c)[0]), "+f"((c)[1]), "+f"((c)[2]), "+f"((c)[3])    \
                 : "r"((a)[0]), "r"((a)[1]), "r"((a)[2]), "r"((a)[3]),       \
                   "r"(b0), "r"(b1))

#define CPA16(dst, src)                                                       \
    asm volatile("cp.async.cg.shared.global [%0], [%1], 16;"                  \
                 :: "r"(dst), "l"(src))

// ---------------- init: tiled eWt transpose + zeros + node encoder ----------------
__global__ void __launch_bounds__(256)
init_kernel(const float* __restrict__ edge_W,
            const float* __restrict__ edge_b,
            const float* __restrict__ root_W,
            const float* __restrict__ x,
            const float* __restrict__ nW,
            const float* __restrict__ nb) {
    int b = blockIdx.x;
    if (b < TTILES_) {
        __shared__ float tile[32][33];
        int c  = b >> 4;
        int t  = b & 15;
        int l  = c / KD_, d = c - l * KD_;
        int n0 = (t >> 2) * 32;
        int k0 = (t & 3) * 32;
        const float* srcp;
        if (d < 16)       srcp = edge_W + ((size_t)(l * 16 + d) << 14);
        else if (d == 16) srcp = edge_b + ((size_t)l << 14);
        else              srcp = root_W + ((size_t)l << 14);
        int tx = threadIdx.x & 31, ty = threadIdx.x >> 5;
#pragma unroll
        for (int q = 0; q < 4; ++q) {
            int kk = k0 + ty + q * 8;
            tile[ty + q * 8][tx] = srcp[kk * H_ + n0 + tx];
        }
        __syncthreads();
        float* dstp = g_eWt + ((size_t)c << 14);
#pragma unroll
        for (int q = 0; q < 4; ++q) {
            int nn = n0 + ty + q * 8;
            dstp[nn * H_ + k0 + tx] = tf32r(tile[tx][ty + q * 8]);
        }
        return;
    }
    int i = (b - TTILES_) * 256 + threadIdx.x;  // covers L*N*H
    if (i < L_ * N_ * H_)  g_agg3[i] = 0.f;
    if (i < G_ * H_)       g_pool[i] = 0.f;
    if (i < L_ * 2 * H_)   g_stats[i] = 0.f;
    if (i < N_ * H_) {
        int n = i >> 7, o = i & 127;
        const float* xr = x + n * ND_;
        float acc = nb[o];
#pragma unroll
        for (int k = 0; k < ND_; ++k) acc += xr[k] * nW[k * H_ + o];
        g_h[i]  = acc;
        g_ht[i] = tf32r(acc);
    }
}

// ---------------- sort: src counting-sort + deg + gcnt, one block ----------------
__global__ void __launch_bounds__(1024)
sort_kernel(const int* __restrict__ edge_index, const int* __restrict__ batch) {
    __shared__ int sa[2048], sb[2048], sc_[2048], cur[2048];
    __shared__ float gcnt[G_];
    int t = threadIdx.x;
#pragma unroll
    for (int q = 0; q < 2; ++q) {
        int i = t + q * 1024;
        sa[i] = 0; sb[i] = 0; cur[i] = 0;
    }
    if (t < G_) gcnt[t] = 0.f;
    __syncthreads();
#pragma unroll
    for (int q = 0; q < 8; ++q) {
        int e = t + q * 1024;
        atomicAdd(&sa[edge_index[e]], 1);
        atomicAdd(&sb[edge_index[E_ + e]], 1);
    }
#pragma unroll
    for (int q = 0; q < 2; ++q) {
        int n = t + q * 1024;
        atomicAdd(&gcnt[batch[n]], 1.f);
    }
    __syncthreads();
    int *s1 = sa, *d1 = sc_;
#pragma unroll
    for (int off = 1; off < 2048; off <<= 1) {
#pragma unroll
        for (int q = 0; q < 2; ++q) {
            int i = t + q * 1024;
            d1[i] = s1[i] + (i >= off ? s1[i - off] : 0);
        }
        __syncthreads();
        int* tmp = s1; s1 = d1; d1 = tmp;
    }
#pragma unroll
    for (int q = 0; q < 2; ++q) {
        int i = t + q * 1024;
        g_soff[i] = i ? s1[i - 1] : 0;
        g_deg[i]  = (float)sb[i];
    }
    if (t < G_) g_gcnt[t] = gcnt[t];
    __syncthreads();
#pragma unroll
    for (int q = 0; q < 8; ++q) {
        int e = t + q * 1024;
        int src = edge_index[e];
        int dst = edge_index[E_ + e];
        int pos = (src ? s1[src - 1] : 0) + atomicAdd(&cur[src], 1);
        g_einfo[pos] = make_int4(src, dst, e, 0);
    }
}

// ---------------- zgemm: z = g_ht @ eWt, K-chunk pipelined cp.async (R14) ----------------
#define ZSA 132
#define ZSMEM_F (256 * ZSA + 128 * ZSA)

__global__ void __launch_bounds__(256, 1)
zgemm_kernel(const float* __restrict__ eWt) {
    extern __shared__ float sm[];

    const int tid  = threadIdx.x;
    const int lane = tid & 31;
    const int wid  = tid >> 5;
    const int wm   = wid >> 1;
    const int wn   = wid & 1;
    const int m0   = blockIdx.x * 256;
    const int d    = blockIdx.y;

    const uint32_t smb = (uint32_t)__cvta_generic_to_shared(sm);
    const float* Bg = eWt + (d << 14);

#pragma unroll
    for (int c = 0; c < 4; ++c) {
        const int kc = c * 32;
#pragma unroll
        for (int jj = 0; jj < 8; ++jj) {
            int idx = tid + jj * 256;
            int r = idx >> 3, f4 = (idx & 7) << 2;
            uint32_t dst = smb + ((r * ZSA + kc + f4) << 2);
            CPA16(dst, g_ht + (m0 + r) * H_ + kc + f4);
        }
#pragma unroll
        for (int jj = 0; jj < 4; ++jj) {
            int idx = tid + jj * 256;
            int r = idx >> 3, f4 = (idx & 7) << 2;
            uint32_t dst = smb + ((256 * ZSA + r * ZSA + kc + f4) << 2);
            CPA16(dst, Bg + r * H_ + kc + f4);
        }
        asm volatile("cp.async.commit_group;");
    }

    const int mrow = (lane & 7) + ((lane >> 3) & 1) * 8;
    const int coff = (lane >> 4) * 4;
    uint32_t aad[4], bad[4];
#pragma unroll
    for (int mt = 0; mt < 4; ++mt)
        aad[mt] = smb + (((wm * 64 + mt * 16 + mrow) * ZSA + coff) << 2);
#pragma unroll
    for (int nt = 0; nt < 4; ++nt)
        bad[nt] = smb + ((256 * ZSA + (wn * 64 + nt * 16 + mrow) * ZSA + coff) << 2);

    float acc[4][8][4];
#pragma unroll
    for (int mt = 0; mt < 4; ++mt)
#pragma unroll
        for (int j = 0; j < 8; ++j)
#pragma unroll
            for (int p = 0; p < 4; ++p) acc[mt][j][p] = 0.f;

    uint32_t Af[2][4][4], Bf[2][4][4];

#define LOAD_STAGE(buf, ko)                                                   \
    do {                                                                      \
        _Pragma("unroll")                                                     \
        for (int mt = 0; mt < 4; ++mt)                                        \
            LDSM4(Af[buf][mt][0], Af[buf][mt][1], Af[buf][mt][2],             \
                  Af[buf][mt][3], aad[mt] + (ko));                            \
        _Pragma("unroll")                                                     \
        for (int nt = 0; nt < 4; ++nt)                                        \
            LDSM4(Bf[buf][nt][0], Bf[buf][nt][1], Bf[buf][nt][2],             \
                  Bf[buf][nt][3], bad[nt] + (ko));                            \
    } while (0)

#pragma unroll
    for (int c = 0; c < 4; ++c) {
        if (c == 0) asm volatile("cp.async.wait_group 3;");
        else if (c == 1) asm volatile("cp.async.wait_group 2;");
        else if (c == 2) asm volatile("cp.async.wait_group 1;");
        else asm volatile("cp.async.wait_group 0;");
        __syncthreads();
        LOAD_STAGE(0, (uint32_t)(c * 4) * 32);
#pragma unroll
        for (int ks = 0; ks < 4; ++ks) {
            const int cur = ks & 1;
            if (ks < 3) {
                const uint32_t ko = (uint32_t)(c * 4 + ks + 1) * 32;
                if (cur == 0) LOAD_STAGE(1, ko); else LOAD_STAGE(0, ko);
            }
#pragma unroll
            for (int nt = 0; nt < 4; ++nt)
#pragma unroll
                for (int mt = 0; mt < 4; ++mt) {
                    MMA_TF32(acc[mt][2 * nt],     Af[cur][mt], Bf[cur][nt][0], Bf[cur][nt][2]);
                    MMA_TF32(acc[mt][2 * nt + 1], Af[cur][mt], Bf[cur][nt][1], Bf[cur][nt][3]);
                }
        }
    }
#undef LOAD_STAGE

    if (d < 17) {
#pragma unroll
        for (int mt = 0; mt < 4; ++mt) {
            int r = m0 + wm * 64 + mt * 16 + (lane >> 2);
            __half* zr0 = g_zh + (size_t)r * ZHW_ + d * H_;
            __half* zr1 = zr0 + 8 * ZHW_;
#pragma unroll
            for (int j = 0; j < 8; ++j) {
                int col = wn * 64 + (j >> 1) * 16 + (j & 1) * 8 + (lane & 3) * 2;
                *reinterpret_cast<__half2*>(zr0 + col) =
                    __floats2half2_rn(acc[mt][j][0], acc[mt][j][1]);
                *reinterpret_cast<__half2*>(zr1 + col) =
                    __floats2half2_rn(acc[mt][j][2], acc[mt][j][3]);
            }
        }
    } else {
#pragma unroll
        for (int mt = 0; mt < 4; ++mt) {
            int r = m0 + wm * 64 + mt * 16 + (lane >> 2);
            float* zr0 = g_zroot + (size_t)r * H_;
            float* zr1 = zr0 + 8 * H_;
#pragma unroll
            for (int j = 0; j < 8; ++j) {
                int col = wn * 64 + (j >> 1) * 16 + (j & 1) * 8 + (lane & 3) * 2;
                *reinterpret_cast<float2*>(zr0 + col) = make_float2(acc[mt][j][0], acc[mt][j][1]);
                *reinterpret_cast<float2*>(zr1 + col) = make_float2(acc[mt][j][2], acc[mt][j][3]);
            }
        }
    }
}

// ---------------- combine: 2 consecutive sorted edges per warp ----------------
// Adjacent sorted edges share src ~75% of the time; the comparison is
// warp-uniform so the shared-z fast path has no divergence.
__global__ void __launch_bounds__(256)
combine_kernel(const float* __restrict__ edge_attr,
               float* __restrict__ aggp) {
    int w    = blockIdx.x * 8 + (threadIdx.x >> 5);
    int lane = threadIdx.x & 31;
    int j0   = w * 2;
    int4 ei0 = g_einfo[j0];
    int4 ei1 = g_einfo[j0 + 1];

    float ea0[16], ea1[16];
    {
        const float4* p0 = reinterpret_cast<const float4*>(edge_attr + ei0.z * ED_);
        const float4* p1 = reinterpret_cast<const float4*>(edge_attr + ei1.z * ED_);
#pragma unroll
        for (int q = 0; q < 4; ++q) {
            float4 v0 = p0[q], v1 = p1[q];
            ea0[4*q] = v0.x; ea0[4*q+1] = v0.y; ea0[4*q+2] = v0.z; ea0[4*q+3] = v0.w;
            ea1[4*q] = v1.x; ea1[4*q+1] = v1.y; ea1[4*q+2] = v1.z; ea1[4*q+3] = v1.w;
        }
    }

    float4 acc0, acc1;
    const __half* zr0 = g_zh + (size_t)ei0.x * ZHW_ + lane * 4;

    if (ei0.x == ei1.x) {
        // shared src: one pass over z rows feeds both accumulators
        uint2 u = *reinterpret_cast<const uint2*>(zr0 + 16 * H_);
        float2 f0 = __half22float2(*reinterpret_cast<__half2*>(&u.x));
        float2 f1 = __half22float2(*reinterpret_cast<__half2*>(&u.y));
        acc0 = make_float4(f0.x, f0.y, f1.x, f1.y);
        acc1 = acc0;
#pragma unroll
        for (int d = 0; d < 16; ++d) {
            uint2 ud = *reinterpret_cast<const uint2*>(zr0 + d * H_);
            float2 g0 = __half22float2(*reinterpret_cast<__half2*>(&ud.x));
            float2 g1 = __half22float2(*reinterpret_cast<__half2*>(&ud.y));
            float a0 = ea0[d], a1 = ea1[d];
            acc0.x += a0 * g0.x; acc0.y += a0 * g0.y;
            acc0.z += a0 * g1.x; acc0.w += a0 * g1.y;
            acc1.x += a1 * g0.x; acc1.y += a1 * g0.y;
            acc1.z += a1 * g1.x; acc1.w += a1 * g1.y;
        }
    } else {
        const __half* zr1 = g_zh + (size_t)ei1.x * ZHW_ + lane * 4;
        {
            uint2 u = *reinterpret_cast<const uint2*>(zr0 + 16 * H_);
            float2 f0 = __half22float2(*reinterpret_cast<__half2*>(&u.x));
            float2 f1 = __half22float2(*reinterpret_cast<__half2*>(&u.y));
            acc0 = make_float4(f0.x, f0.y, f1.x, f1.y);
        }
        {
            uint2 u = *reinterpret_cast<const uint2*>(zr1 + 16 * H_);
            float2 f0 = __half22float2(*reinterpret_cast<__half2*>(&u.x));
            float2 f1 = __half22float2(*reinterpret_cast<__half2*>(&u.y));
            acc1 = make_float4(f0.x, f0.y, f1.x, f1.y);
        }
#pragma unroll
        for (int d = 0; d < 16; ++d) {
            uint2 u0 = *reinterpret_cast<const uint2*>(zr0 + d * H_);
            uint2 u1 = *reinterpret_cast<const uint2*>(zr1 + d * H_);
            float2 g00 = __half22float2(*reinterpret_cast<__half2*>(&u0.x));
            float2 g01 = __half22float2(*reinterpret_cast<__half2*>(&u0.y));
            float2 g10 = __half22float2(*reinterpret_cast<__half2*>(&u1.x));
            float2 g11 = __half22float2(*reinterpret_cast<__half2*>(&u1.y));
            float a0 = ea0[d], a1 = ea1[d];
            acc0.x += a0 * g00.x; acc0.y += a0 * g00.y;
            acc0.z += a0 * g01.x; acc0.w += a0 * g01.y;
            acc1.x += a1 * g10.x; acc1.y += a1 * g10.y;
            acc1.z += a1 * g11.x; acc1.w += a1 * g11.y;
        }
    }

    float* ap0 = aggp + ei0.y * H_ + lane * 4;
    asm volatile("red.global.add.v4.f32 [%0], {%1,%2,%3,%4};"
                 :: "l"(ap0), "f"(acc0.x), "f"(acc0.y), "f"(acc0.z), "f"(acc0.w)
                 : "memory");
    float* ap1 = aggp + ei1.y * H_ + lane * 4;
    asm volatile("red.global.add.v4.f32 [%0], {%1,%2,%3,%4};"
                 :: "l"(ap1), "f"(acc1.x), "f"(acc1.y), "f"(acc1.z), "f"(acc1.w)
                 : "memory");
}

// ---------------- x_new = zroot + agg/deg + bias ; BN stats ----------------
__global__ void __launch_bounds__(256)
xnew_kernel(const float* __restrict__ cbias,
            const float* __restrict__ aggp, float* __restrict__ statp) {
    __shared__ float ps[128], pq[128];
    int o    = threadIdx.x & 127;
    int half = threadIdx.x >> 7;
    int r0   = blockIdx.x * 16 + half * 8;
    float cb = cbias[o];
    float s = 0.f, sq = 0.f;
#pragma unroll
    for (int r = 0; r < 8; ++r) {
        int n = r0 + r;
        float v = g_zroot[(size_t)n * H_ + o]
                + aggp[n * H_ + o] / fmaxf(g_deg[n], 1.f) + cb;
        g_xnew[n * H_ + o] = v;
        s += v;
        sq += v * v;
    }
    if (half) { ps[o] = s; pq[o] = sq; }
    __syncthreads();
    if (!half) {
        atomicAdd(&statp[o],      s  + ps[o]);
        atomicAdd(&statp[H_ + o], sq + pq[o]);
    }
}

// ---------------- BN + ReLU + residual (+ pool on last layer) ----------------
__global__ void bn_kernel(const float* __restrict__ gamma,
                          const float* __restrict__ beta,
                          const float* __restrict__ statp,
                          const int* __restrict__ batch, int last) {
    int idx = blockIdx.x * 256 + threadIdx.x;   // N*H threads
    int o = idx & (H_ - 1);
    float mu  = statp[o] * (1.f / N_);
    float var = statp[H_ + o] * (1.f / N_) - mu * mu;
    float v = (g_xnew[idx] - mu) * rsqrtf(var + BN_EPS) * gamma[o] + beta[o];
    float hv = g_h[idx] + fmaxf(v, 0.f);
    g_h[idx]  = hv;
    g_ht[idx] = tf32r(hv);
    if (last) {
        int n = idx >> 7;
        atomicAdd(&g_pool[batch[n] * H_ + o], hv);
    }
}

// ---------------- classifier ----------------
__global__ void __launch_bounds__(64)
cls_kernel(const float* __restrict__ W1, const float* __restrict__ b1,
           const float* __restrict__ W2, const float* __restrict__ b2,
           float* __restrict__ out) {
    __shared__ float gv[H_];
    __shared__ float part[2];
    int g = blockIdx.x, j = threadIdx.x;
    float inv = 1.f / fmaxf(g_gcnt[g], 1.f);
    gv[j]      = g_pool[g * H_ + j] * inv;
    gv[j + 64] = g_pool[g * H_ + 64 + j] * inv;
    __syncthreads();
    float a = b1[j];
    for (int k = 0; k < H_; ++k) a += gv[k] * W1[k * 64 + j];
    float v = fmaxf(a, 0.f) * W2[j];
#pragma unroll
    for (int off = 16; off > 0; off >>= 1)
        v += __shfl_down_sync(0xffffffffu, v, off);
    if ((j & 31) == 0) part[j >> 5] = v;
    __syncthreads();
    if (j == 0) out[g] = part[0] + part[1] + b2[0];
}

// ---------------- launch ----------------
extern "C" void kernel_launch(void* const* d_in, const int* in_sizes, int n_in,
                              void* d_out, int out_size) {
    const float* x          = (const float*)d_in[0];
    const int*   edge_index = (const int*)  d_in[1];
    const float* edge_attr  = (const float*)d_in[2];
    const int*   batch      = (const int*)  d_in[3];
    const float* node_W     = (const float*)d_in[4];
    const float* node_b     = (const float*)d_in[5];
    const float* edge_W     = (const float*)d_in[6];
    const float* edge_b     = (const float*)d_in[7];
    const float* root_W     = (const float*)d_in[8];
    const float* conv_bias  = (const float*)d_in[9];
    const float* bn_gamma   = (const float*)d_in[10];
    const float* bn_beta    = (const float*)d_in[11];
    const float* cls_W1     = (const float*)d_in[12];
    const float* cls_b1     = (const float*)d_in[13];
    const float* cls_W2     = (const float*)d_in[14];
    const float* cls_b2     = (const float*)d_in[15];
    float* out = (float*)d_out;

    float* d_agg3;  cudaGetSymbolAddress((void**)&d_agg3,  g_agg3);
    float* d_stats; cudaGetSymbolAddress((void**)&d_stats, g_stats);
    float* d_eWt;   cudaGetSymbolAddress((void**)&d_eWt,   g_eWt);

    const int zsmem = ZSMEM_F * 4;   // ~198 KB
    cudaFuncSetAttribute((const void*)zgemm_kernel,
                         cudaFuncAttributeMaxDynamicSharedMemorySize, zsmem);

    init_kernel<<<TTILES_ + (L_ * N_ * H_) / 256, 256>>>(
        edge_W, edge_b, root_W, x, node_W, node_b);
    sort_kernel<<<1, 1024>>>(edge_index, batch);

    for (int l = 0; l < L_; ++l) {
        zgemm_kernel<<<dim3(N_ / 256, KD_), 256, zsmem>>>(
            d_eWt + (size_t)l * KD_ * H_ * H_);
        combine_kernel<<<E_ / 16, 256>>>(edge_attr,
                                         d_agg3 + (size_t)l * N_ * H_);
        xnew_kernel<<<N_ / 16, 256>>>(conv_bias + l * H_,
                                      d_agg3 + (size_t)l * N_ * H_,
                                      d_stats + l * 2 * H_);
        bn_kernel<<<(N_ * H_) / 256, 256>>>(bn_gamma + l * H_, bn_beta + l * H_,
                                            d_stats + l * 2 * H_, batch,
                                            l == L_ - 1);
    }

    cls_kernel<<<G_, 64>>>(cls_W1, cls_b1, cls_W2, cls_b2, out);
}

// round 17
// speedup vs baseline: 1.4674x; 1.1598x over previous
#include <cuda_runtime.h>
#include <cuda_fp16.h>
#include <cstdint>

#define N_  2048
#define E_  8192
#define ND_ 32
#define ED_ 16
#define H_  128
#define G_  128
#define L_  3
#define KD_ 18          // 16 edge dims + edge bias + root_W
#define ZHW_ (17 * H_)  // 2176 halves per node (conv chunks)
#define BN_EPS 1e-5f

#define TTILES_ (L_ * KD_ * 16)   // 864 transpose tiles (32x32), 16 per chunk

// ---------------- device scratch ----------------
__device__ float  g_h[N_ * H_];
__device__ __half g_hh[N_ * H_];                // fp16 copy of h (GEMM A input)
__device__ float  g_xnew[N_ * H_];
__device__ float  g_agg3[L_ * N_ * H_];
__device__ float  g_deg[N_];
__device__ float  g_stats[L_ * 2 * H_];
__device__ float  g_pool[G_ * H_];
__device__ float  g_gcnt[G_];
__device__ __half g_zh[N_ * ZHW_];              // fp16 conv-chunk z, 8.9MB
__device__ float  g_zroot[N_ * H_];             // fp32 root chunk
__device__ __half g_eWt[L_ * KD_ * H_ * H_];    // fp16, [l][d][n=o][k=i]
__device__ int    g_soff[N_];
__device__ int4   g_einfo[E_];                  // (src, dst, e, pad) per sorted pos

// ---------------- helpers ----------------
#define LDSM4(r0, r1, r2, r3, addr)                                          \
    asm volatile("ldmatrix.sync.aligned.m8n8.x4.shared.b16 {%0,%1,%2,%3}, [%4];" \
                 : "=r"(r0), "=r"(r1), "=r"(r2), "=r"(r3) : "r"(addr))

// fp16 mma: D(f32) += A(f16 m16k16) * B(f16 k16n8)
#define MMA_F16(c, a, b0, b1)                                                \
    asm volatile("mma.sync.aligned.m16n8k16.row.col.f32.f16.f16.f32 "        \
                 "{%0,%1,%2,%3}, {%4,%5,%6,%7}, {%8,%9}, {%0,%1,%2,%3};"     \
                 : "+f"((c)[0]), "+f"((c)[1]), "+f"((c)[2]), "+f"((c)[3])    \
                 : "r"((a)[0]), "r"((a)[1]), "r"((a)[2]), "r"((a)[3]),       \
                   "r"(b0), "r"(b1))

#define CPA16(dst, src)                                                       \
    asm volatile("cp.async.cg.shared.global [%0], [%1], 16;"                  \
                 :: "r"(dst), "l"(src))

// ---------------- init: tiled eWt transpose(+fp16) + zeros + node encoder ----------------
__global__ void __launch_bounds__(256)
init_kernel(const float* __restrict__ edge_W,
            const float* __restrict__ edge_b,
            const float* __restrict__ root_W,
            const float* __restrict__ x,
            const float* __restrict__ nW,
            const float* __restrict__ nb) {
    int b = blockIdx.x;
    if (b < TTILES_) {
        __shared__ float tile[32][33];
        int c  = b >> 4;
        int t  = b & 15;
        int l  = c / KD_, d = c - l * KD_;
        int n0 = (t >> 2) * 32;
        int k0 = (t & 3) * 32;
        const float* srcp;
        if (d < 16)       srcp = edge_W + ((size_t)(l * 16 + d) << 14);
        else if (d == 16) srcp = edge_b + ((size_t)l << 14);
        else              srcp = root_W + ((size_t)l << 14);
        int tx = threadIdx.x & 31, ty = threadIdx.x >> 5;
#pragma unroll
        for (int q = 0; q < 4; ++q) {
            int kk = k0 + ty + q * 8;
            tile[ty + q * 8][tx] = srcp[kk * H_ + n0 + tx];
        }
        __syncthreads();
        __half* dstp = g_eWt + ((size_t)c << 14);
#pragma unroll
        for (int q = 0; q < 4; ++q) {
            int nn = n0 + ty + q * 8;
            dstp[nn * H_ + k0 + tx] = __float2half_rn(tile[tx][ty + q * 8]);
        }
        return;
    }
    int i = (b - TTILES_) * 256 + threadIdx.x;  // covers L*N*H
    if (i < L_ * N_ * H_)  g_agg3[i] = 0.f;
    if (i < G_ * H_)       g_pool[i] = 0.f;
    if (i < L_ * 2 * H_)   g_stats[i] = 0.f;
    if (i < N_ * H_) {
        int n = i >> 7, o = i & 127;
        const float* xr = x + n * ND_;
        float acc = nb[o];
#pragma unroll
        for (int k = 0; k < ND_; ++k) acc += xr[k] * nW[k * H_ + o];
        g_h[i]  = acc;
        g_hh[i] = __float2half_rn(acc);
    }
}

// ---------------- sort: src counting-sort + deg + gcnt, one block ----------------
__global__ void __launch_bounds__(1024)
sort_kernel(const int* __restrict__ edge_index, const int* __restrict__ batch) {
    __shared__ int sa[2048], sb[2048], sc_[2048], cur[2048];
    __shared__ float gcnt[G_];
    int t = threadIdx.x;
#pragma unroll
    for (int q = 0; q < 2; ++q) {
        int i = t + q * 1024;
        sa[i] = 0; sb[i] = 0; cur[i] = 0;
    }
    if (t < G_) gcnt[t] = 0.f;
    __syncthreads();
#pragma unroll
    for (int q = 0; q < 8; ++q) {
        int e = t + q * 1024;
        atomicAdd(&sa[edge_index[e]], 1);
        atomicAdd(&sb[edge_index[E_ + e]], 1);
    }
#pragma unroll
    for (int q = 0; q < 2; ++q) {
        int n = t + q * 1024;
        atomicAdd(&gcnt[batch[n]], 1.f);
    }
    __syncthreads();
    int *s1 = sa, *d1 = sc_;
#pragma unroll
    for (int off = 1; off < 2048; off <<= 1) {
#pragma unroll
        for (int q = 0; q < 2; ++q) {
            int i = t + q * 1024;
            d1[i] = s1[i] + (i >= off ? s1[i - off] : 0);
        }
        __syncthreads();
        int* tmp = s1; s1 = d1; d1 = tmp;
    }
#pragma unroll
    for (int q = 0; q < 2; ++q) {
        int i = t + q * 1024;
        g_soff[i] = i ? s1[i - 1] : 0;
        g_deg[i]  = (float)sb[i];
    }
    if (t < G_) g_gcnt[t] = gcnt[t];
    __syncthreads();
#pragma unroll
    for (int q = 0; q < 8; ++q) {
        int e = t + q * 1024;
        int src = edge_index[e];
        int dst = edge_index[E_ + e];
        int pos = (src ? s1[src - 1] : 0) + atomicAdd(&cur[src], 1);
        g_einfo[pos] = make_int4(src, dst, e, 0);
    }
}

// ---------------- zgemm: z = g_hh @ eWt, fp16 MMA, 2 K-chunks x 4 ksteps ----------------
#define ZSA 136                         // halves per smem row (128 + 8 pad)
#define ZSMEM_B ((256 + 128) * ZSA * 2) // ~102 KB

__global__ void __launch_bounds__(256, 1)
zgemm_kernel(const __half* __restrict__ eWt) {
    extern __shared__ __half smh[];
    const int tid  = threadIdx.x;
    const int lane = tid & 31;
    const int wid  = tid >> 5;
    const int wm   = wid >> 1;
    const int wn   = wid & 1;
    const int m0   = blockIdx.x * 256;
    const int d    = blockIdx.y;

    const uint32_t smb = (uint32_t)__cvta_generic_to_shared(smh);
    const uint32_t boff = 256 * ZSA * 2;     // B base byte offset
    const __half* Bg = eWt + ((size_t)d << 14);

    // ---- stage A+B in 2 K-chunks of 64 halves (128B/row), one group each ----
#pragma unroll
    for (int c = 0; c < 2; ++c) {
        const int kc = c * 64;               // halves
        // A: 256 rows x 8 chunks of 8 halves -> 2048 cp16 / 8 per thread
#pragma unroll
        for (int jj = 0; jj < 8; ++jj) {
            int idx = tid + jj * 256;
            int r = idx >> 3, f8 = (idx & 7) << 3;
            uint32_t dst = smb + (r * ZSA + kc + f8) * 2;
            CPA16(dst, g_hh + (m0 + r) * H_ + kc + f8);
        }
        // B: 128 rows -> 1024 cp16 / 4 per thread
#pragma unroll
        for (int jj = 0; jj < 4; ++jj) {
            int idx = tid + jj * 256;
            int r = idx >> 3, f8 = (idx & 7) << 3;
            uint32_t dst = smb + boff + (r * ZSA + kc + f8) * 2;
            CPA16(dst, Bg + r * H_ + kc + f8);
        }
        asm volatile("cp.async.commit_group;");
    }

    // ldmatrix addresses: mrow covers 0-7/8-15 per lane octet; coff = 8-half col group
    const int mrow = (lane & 7) + ((lane >> 3) & 1) * 8;
    const int coff = (lane >> 4) * 8;        // halves
    uint32_t aad[4], bad[4];
#pragma unroll
    for (int mt = 0; mt < 4; ++mt)
        aad[mt] = smb + ((wm * 64 + mt * 16 + mrow) * ZSA + coff) * 2;
#pragma unroll
    for (int nt = 0; nt < 4; ++nt)
        bad[nt] = smb + boff + ((wn * 64 + nt * 16 + mrow) * ZSA + coff) * 2;

    float acc[4][8][4];
#pragma unroll
    for (int mt = 0; mt < 4; ++mt)
#pragma unroll
        for (int j = 0; j < 8; ++j)
#pragma unroll
            for (int p = 0; p < 4; ++p) acc[mt][j][p] = 0.f;

    uint32_t Af[2][4][4], Bf[2][4][4];

#define LOAD_STAGE(buf, ko)                                                   \
    do {                                                                      \
        _Pragma("unroll")                                                     \
        for (int mt = 0; mt < 4; ++mt)                                        \
            LDSM4(Af[buf][mt][0], Af[buf][mt][1], Af[buf][mt][2],             \
                  Af[buf][mt][3], aad[mt] + (ko));                            \
        _Pragma("unroll")                                                     \
        for (int nt = 0; nt < 4; ++nt)                                        \
            LDSM4(Bf[buf][nt][0], Bf[buf][nt][1], Bf[buf][nt][2],             \
                  Bf[buf][nt][3], bad[nt] + (ko));                            \
    } while (0)

    // ---- 2 chunks x 4 ksteps (k16 each = 32B offset per kstep) ----
#pragma unroll
    for (int c = 0; c < 2; ++c) {
        if (c == 0) asm volatile("cp.async.wait_group 1;");
        else        asm volatile("cp.async.wait_group 0;");
        __syncthreads();
        LOAD_STAGE(0, (uint32_t)(c * 4) * 32);
#pragma unroll
        for (int ks = 0; ks < 4; ++ks) {
            const int cur = ks & 1;
            if (ks < 3) {
                const uint32_t ko = (uint32_t)(c * 4 + ks + 1) * 32;
                if (cur == 0) LOAD_STAGE(1, ko); else LOAD_STAGE(0, ko);
            }
#pragma unroll
            for (int nt = 0; nt < 4; ++nt)
#pragma unroll
                for (int mt = 0; mt < 4; ++mt) {
                    MMA_F16(acc[mt][2 * nt],     Af[cur][mt], Bf[cur][nt][0], Bf[cur][nt][2]);
                    MMA_F16(acc[mt][2 * nt + 1], Af[cur][mt], Bf[cur][nt][1], Bf[cur][nt][3]);
                }
        }
    }
#undef LOAD_STAGE

    // ---- epilogue: conv chunks -> fp16 g_zh, root chunk -> fp32 g_zroot ----
    if (d < 17) {
#pragma unroll
        for (int mt = 0; mt < 4; ++mt) {
            int r = m0 + wm * 64 + mt * 16 + (lane >> 2);
            __half* zr0 = g_zh + (size_t)r * ZHW_ + d * H_;
            __half* zr1 = zr0 + 8 * ZHW_;
#pragma unroll
            for (int j = 0; j < 8; ++j) {
                int col = wn * 64 + (j >> 1) * 16 + (j & 1) * 8 + (lane & 3) * 2;
                *reinterpret_cast<__half2*>(zr0 + col) =
                    __floats2half2_rn(acc[mt][j][0], acc[mt][j][1]);
                *reinterpret_cast<__half2*>(zr1 + col) =
                    __floats2half2_rn(acc[mt][j][2], acc[mt][j][3]);
            }
        }
    } else {
#pragma unroll
        for (int mt = 0; mt < 4; ++mt) {
            int r = m0 + wm * 64 + mt * 16 + (lane >> 2);
            float* zr0 = g_zroot + (size_t)r * H_;
            float* zr1 = zr0 + 8 * H_;
#pragma unroll
            for (int j = 0; j < 8; ++j) {
                int col = wn * 64 + (j >> 1) * 16 + (j & 1) * 8 + (lane & 3) * 2;
                *reinterpret_cast<float2*>(zr0 + col) = make_float2(acc[mt][j][0], acc[mt][j][1]);
                *reinterpret_cast<float2*>(zr1 + col) = make_float2(acc[mt][j][2], acc[mt][j][3]);
            }
        }
    }
}

// ---------------- combine: R14-exact warp per edge, fp16 gather, v4 reduction ----------------
__global__ void __launch_bounds__(256)
combine_kernel(const float* __restrict__ edge_attr,
               float* __restrict__ aggp) {
    int j    = blockIdx.x * 8 + (threadIdx.x >> 5);
    int lane = threadIdx.x & 31;
    int4 ei = g_einfo[j];                 // (src, dst, e)
    int src = ei.x, dst = ei.y, e = ei.z;

    float ea[16];
    {
        const float4* eap = reinterpret_cast<const float4*>(edge_attr + e * ED_);
#pragma unroll
        for (int q = 0; q < 4; ++q) {
            float4 v = eap[q];
            ea[4 * q] = v.x; ea[4 * q + 1] = v.y; ea[4 * q + 2] = v.z; ea[4 * q + 3] = v.w;
        }
    }

    const __half* zr = g_zh + (size_t)src * ZHW_ + lane * 4;
    float4 acc;
    {
        uint2 u = *reinterpret_cast<const uint2*>(zr + 16 * H_);   // bias chunk
        float2 f0 = __half22float2(*reinterpret_cast<__half2*>(&u.x));
        float2 f1 = __half22float2(*reinterpret_cast<__half2*>(&u.y));
        acc = make_float4(f0.x, f0.y, f1.x, f1.y);
    }
#pragma unroll
    for (int d = 0; d < 16; ++d) {
        uint2 u = *reinterpret_cast<const uint2*>(zr + d * H_);
        float2 f0 = __half22float2(*reinterpret_cast<__half2*>(&u.x));
        float2 f1 = __half22float2(*reinterpret_cast<__half2*>(&u.y));
        float a = ea[d];
        acc.x += a * f0.x; acc.y += a * f0.y;
        acc.z += a * f1.x; acc.w += a * f1.y;
    }
    float* ap = aggp + dst * H_ + lane * 4;
    asm volatile("red.global.add.v4.f32 [%0], {%1,%2,%3,%4};"
                 :: "l"(ap), "f"(acc.x), "f"(acc.y), "f"(acc.z), "f"(acc.w)
                 : "memory");
}

// ---------------- x_new = zroot + agg/deg + bias ; BN stats ----------------
__global__ void __launch_bounds__(256)
xnew_kernel(const float* __restrict__ cbias,
            const float* __restrict__ aggp, float* __restrict__ statp) {
    __shared__ float ps[128], pq[128];
    int o    = threadIdx.x & 127;
    int half = threadIdx.x >> 7;
    int r0   = blockIdx.x * 16 + half * 8;
    float cb = cbias[o];
    float s = 0.f, sq = 0.f;
#pragma unroll
    for (int r = 0; r < 8; ++r) {
        int n = r0 + r;
        float v = g_zroot[(size_t)n * H_ + o]
                + aggp[n * H_ + o] / fmaxf(g_deg[n], 1.f) + cb;
        g_xnew[n * H_ + o] = v;
        s += v;
        sq += v * v;
    }
    if (half) { ps[o] = s; pq[o] = sq; }
    __syncthreads();
    if (!half) {
        atomicAdd(&statp[o],      s  + ps[o]);
        atomicAdd(&statp[H_ + o], sq + pq[o]);
    }
}

// ---------------- BN + ReLU + residual (+ pool on last layer) ----------------
__global__ void bn_kernel(const float* __restrict__ gamma,
                          const float* __restrict__ beta,
                          const float* __restrict__ statp,
                          const int* __restrict__ batch, int last) {
    int idx = blockIdx.x * 256 + threadIdx.x;   // N*H threads
    int o = idx & (H_ - 1);
    float mu  = statp[o] * (1.f / N_);
    float var = statp[H_ + o] * (1.f / N_) - mu * mu;
    float v = (g_xnew[idx] - mu) * rsqrtf(var + BN_EPS) * gamma[o] + beta[o];
    float hv = g_h[idx] + fmaxf(v, 0.f);
    g_h[idx]  = hv;
    g_hh[idx] = __float2half_rn(hv);
    if (last) {
        int n = idx >> 7;
        atomicAdd(&g_pool[batch[n] * H_ + o], hv);
    }
}

// ---------------- classifier ----------------
__global__ void __launch_bounds__(64)
cls_kernel(const float* __restrict__ W1, const float* __restrict__ b1,
           const float* __restrict__ W2, const float* __restrict__ b2,
           float* __restrict__ out) {
    __shared__ float gv[H_];
    __shared__ float part[2];
    int g = blockIdx.x, j = threadIdx.x;
    float inv = 1.f / fmaxf(g_gcnt[g], 1.f);
    gv[j]      = g_pool[g * H_ + j] * inv;
    gv[j + 64] = g_pool[g * H_ + 64 + j] * inv;
    __syncthreads();
    float a = b1[j];
    for (int k = 0; k < H_; ++k) a += gv[k] * W1[k * 64 + j];
    float v = fmaxf(a, 0.f) * W2[j];
#pragma unroll
    for (int off = 16; off > 0; off >>= 1)
        v += __shfl_down_sync(0xffffffffu, v, off);
    if ((j & 31) == 0) part[j >> 5] = v;
    __syncthreads();
    if (j == 0) out[g] = part[0] + part[1] + b2[0];
}

// ---------------- launch ----------------
extern "C" void kernel_launch(void* const* d_in, const int* in_sizes, int n_in,
                              void* d_out, int out_size) {
    const float* x          = (const float*)d_in[0];
    const int*   edge_index = (const int*)  d_in[1];
    const float* edge_attr  = (const float*)d_in[2];
    const int*   batch      = (const int*)  d_in[3];
    const float* node_W     = (const float*)d_in[4];
    const float* node_b     = (const float*)d_in[5];
    const float* edge_W     = (const float*)d_in[6];
    const float* edge_b     = (const float*)d_in[7];
    const float* root_W     = (const float*)d_in[8];
    const float* conv_bias  = (const float*)d_in[9];
    const float* bn_gamma   = (const float*)d_in[10];
    const float* bn_beta    = (const float*)d_in[11];
    const float* cls_W1     = (const float*)d_in[12];
    const float* cls_b1     = (const float*)d_in[13];
    const float* cls_W2     = (const float*)d_in[14];
    const float* cls_b2     = (const float*)d_in[15];
    float* out = (float*)d_out;

    float*  d_agg3;  cudaGetSymbolAddress((void**)&d_agg3,  g_agg3);
    float*  d_stats; cudaGetSymbolAddress((void**)&d_stats, g_stats);
    __half* d_eWt;   cudaGetSymbolAddress((void**)&d_eWt,   g_eWt);

    cudaFuncSetAttribute((const void*)zgemm_kernel,
                         cudaFuncAttributeMaxDynamicSharedMemorySize, ZSMEM_B);

    init_kernel<<<TTILES_ + (L_ * N_ * H_) / 256, 256>>>(
        edge_W, edge_b, root_W, x, node_W, node_b);
    sort_kernel<<<1, 1024>>>(edge_index, batch);

    for (int l = 0; l < L_; ++l) {
        zgemm_kernel<<<dim3(N_ / 256, KD_), 256, ZSMEM_B>>>(
            d_eWt + (size_t)l * KD_ * H_ * H_);
        combine_kernel<<<E_ / 8, 256>>>(edge_attr,
                                        d_agg3 + (size_t)l * N_ * H_);
        xnew_kernel<<<N_ / 16, 256>>>(conv_bias + l * H_,
                                      d_agg3 + (size_t)l * N_ * H_,
                                      d_stats + l * 2 * H_);
        bn_kernel<<<(N_ * H_) / 256, 256>>>(bn_gamma + l * H_, bn_beta + l * H_,
                                            d_stats + l * 2 * H_, batch,
                                            l == L_ - 1);
    }

    cls_kernel<<<G_, 64>>>(cls_W1, cls_b1, cls_W2, cls_b2, out);
}